// round 1
// baseline (speedup 1.0000x reference)
#include <cuda_runtime.h>
#include <stdint.h>

// Problem constants
constexpr int NB = 8;
constexpr int NC = 3;
constexpr int IMG_H = 1024;
constexpr int IMG_W = 1024;
constexpr int N_SPOTS = 15728;

// Gaussian 1D weights for ksize=5, sigma=1.5 (normalized, double-precision derived)
#define G0 0.12007838424f
#define G1 0.23388075658f
#define G2 0.29208171834f

// Per-batch snow mask (8 MB). __device__ global => no allocation in kernel_launch.
__device__ __align__(16) unsigned char g_mask[NB * IMG_H * IMG_W];

// ---------------------------------------------------------------------------
// Kernel 1: zero the mask (uint4 stores, 512K threads)
// ---------------------------------------------------------------------------
__global__ void zero_mask_kernel() {
    int i = blockIdx.x * blockDim.x + threadIdx.x;
    constexpr int N16 = NB * IMG_H * IMG_W / 16;
    uint4* p = reinterpret_cast<uint4*>(g_mask);
    if (i < N16) p[i] = make_uint4(0u, 0u, 0u, 0u);
}

// ---------------------------------------------------------------------------
// Kernel 2: scatter snow boxes. One thread per (batch, spot).
// radius = rs+1 in {1,2,3}; box clipped to image. Races are benign (all write 1).
// ---------------------------------------------------------------------------
__global__ void scatter_kernel(const int* __restrict__ ys,
                               const int* __restrict__ xs,
                               const int* __restrict__ rs) {
    int i = blockIdx.x * blockDim.x + threadIdx.x;
    if (i >= NB * N_SPOTS) return;
    int b = i / N_SPOTS;
    int y = ys[i];
    int x = xs[i];
    int r = rs[i] + 1;
    unsigned char* m = g_mask + (size_t)b * IMG_H * IMG_W;
    int y0 = y - r; if (y0 < 0) y0 = 0;
    int y1 = y + r; if (y1 > IMG_H - 1) y1 = IMG_H - 1;
    int x0 = x - r; if (x0 < 0) x0 = 0;
    int x1 = x + r; if (x1 > IMG_W - 1) x1 = IMG_W - 1;
    for (int yy = y0; yy <= y1; yy++) {
        unsigned char* row = m + yy * IMG_W;
        for (int xx = x0; xx <= x1; xx++) row[xx] = 1;
    }
}

// ---------------------------------------------------------------------------
// Kernel 3: fused mask-substitute + separable 5x5 Gaussian + clip.
// Block: 32x8 threads, output tile 32(w) x 32(h).
// Smem: raw masked tile 36x36 (pitch 37, bank-conflict-free for the 4-wide
// horizontal pass), then horizontally-filtered tile 36x32 (pitch 32).
// ---------------------------------------------------------------------------
__global__ __launch_bounds__(256) void snow_blur_kernel(const float* __restrict__ x,
                                                        float* __restrict__ out) {
    __shared__ float raw[36 * 37];
    __shared__ float hf[36 * 32];

    const int bx = blockIdx.x;          // W tile
    const int by = blockIdx.y;          // H tile
    const int bc = blockIdx.z;          // b*NC + c
    const int b = bc / NC;

    const float* xp = x + (size_t)bc * IMG_H * IMG_W;
    float* op = out + (size_t)bc * IMG_H * IMG_W;
    const unsigned char* mp = g_mask + (size_t)b * IMG_H * IMG_W;

    const int tx = threadIdx.x;
    const int ty = threadIdx.y;
    const int tid = ty * 32 + tx;

    const int y0 = by * 32 - 2;         // top-left of raw tile in image coords
    const int x0 = bx * 32 - 2;

    // Phase 1: load masked input (zero padding outside image)
    #pragma unroll
    for (int i = tid; i < 36 * 36; i += 256) {
        int r = i / 36;
        int c = i - r * 36;
        int gy = y0 + r;
        int gx = x0 + c;
        float v = 0.0f;
        if ((unsigned)gy < (unsigned)IMG_H && (unsigned)gx < (unsigned)IMG_W) {
            int idx = gy * IMG_W + gx;
            v = mp[idx] ? 0.95f : xp[idx];
        }
        raw[r * 37 + c] = v;
    }
    __syncthreads();

    // Phase 2: horizontal filter. 36 rows x 32 cols of Hf, 4-wide per task.
    // Hf[r][c] = sum_{k=0..4} g[k] * raw[r][c+k]
    #pragma unroll
    for (int t = tid; t < 36 * 8; t += 256) {
        int r = t >> 3;
        int cs = (t & 7) * 4;
        const float* rr = raw + r * 37 + cs;
        float v0 = rr[0], v1 = rr[1], v2 = rr[2], v3 = rr[3];
        float v4 = rr[4], v5 = rr[5], v6 = rr[6], v7 = rr[7];
        float* hr = hf + r * 32 + cs;
        hr[0] = G0 * v0 + G1 * v1 + G2 * v2 + G1 * v3 + G0 * v4;
        hr[1] = G0 * v1 + G1 * v2 + G2 * v3 + G1 * v4 + G0 * v5;
        hr[2] = G0 * v2 + G1 * v3 + G2 * v4 + G1 * v5 + G0 * v6;
        hr[3] = G0 * v3 + G1 * v4 + G2 * v5 + G1 * v6 + G0 * v7;
    }
    __syncthreads();

    // Phase 3: vertical filter, 4 contiguous output rows per thread.
    // out[j] = sum_{k=0..4} g[k] * Hf[j+k]   (Hf row j corresponds to image row y0+j)
    {
        const int r0 = ty * 4;           // output tile rows r0..r0+3
        const float* hc = hf + r0 * 32 + tx;
        float a0 = hc[0 * 32], a1 = hc[1 * 32], a2 = hc[2 * 32], a3 = hc[3 * 32];
        float a4 = hc[4 * 32], a5 = hc[5 * 32], a6 = hc[6 * 32], a7 = hc[7 * 32];

        float o0 = G0 * a0 + G1 * a1 + G2 * a2 + G1 * a3 + G0 * a4;
        float o1 = G0 * a1 + G1 * a2 + G2 * a3 + G1 * a4 + G0 * a5;
        float o2 = G0 * a2 + G1 * a3 + G2 * a4 + G1 * a5 + G0 * a6;
        float o3 = G0 * a3 + G1 * a4 + G2 * a5 + G1 * a6 + G0 * a7;

        o0 = fminf(fmaxf(o0, 0.0f), 1.0f);
        o1 = fminf(fmaxf(o1, 0.0f), 1.0f);
        o2 = fminf(fmaxf(o2, 0.0f), 1.0f);
        o3 = fminf(fmaxf(o3, 0.0f), 1.0f);

        const int gy = by * 32 + r0;
        const int gx = bx * 32 + tx;
        float* po = op + gy * IMG_W + gx;
        po[0 * IMG_W] = o0;
        po[1 * IMG_W] = o1;
        po[2 * IMG_W] = o2;
        po[3 * IMG_W] = o3;
    }
}

// ---------------------------------------------------------------------------
// Launch
// ---------------------------------------------------------------------------
extern "C" void kernel_launch(void* const* d_in, const int* in_sizes, int n_in,
                              void* d_out, int out_size) {
    const float* x  = (const float*)d_in[0];
    const int*   ys = (const int*)d_in[1];
    const int*   xs = (const int*)d_in[2];
    const int*   rs = (const int*)d_in[3];
    float* out = (float*)d_out;

    // 1) zero mask
    constexpr int N16 = NB * IMG_H * IMG_W / 16;
    zero_mask_kernel<<<(N16 + 255) / 256, 256>>>();

    // 2) scatter snow boxes
    constexpr int NSP = NB * N_SPOTS;
    scatter_kernel<<<(NSP + 255) / 256, 256>>>(ys, xs, rs);

    // 3) fused mask + separable blur + clip
    dim3 grid(IMG_W / 32, IMG_H / 32, NB * NC);
    dim3 block(32, 8);
    snow_blur_kernel<<<grid, block>>>(x, out);
}

// round 3
// speedup vs baseline: 1.5934x; 1.5934x over previous
#include <cuda_runtime.h>
#include <stdint.h>

// Problem constants
constexpr int NB = 8;
constexpr int NC = 3;
constexpr int IMG_H = 1024;
constexpr int IMG_W = 1024;
constexpr int N_SPOTS = 15728;

// Gaussian 1D weights for ksize=5, sigma=1.5 (normalized)
#define G0 0.12007838424f
#define G1 0.23388075658f
#define G2 0.29208171834f

// Tile geometry for the conv kernel
constexpr int TW = 128;          // output tile width
constexpr int TH = 16;           // output tile height
constexpr int RAW_W = TW + 8;    // 136 floats per raw row (image cols [-4, 131])
constexpr int RAW_H = TH + 4;    // 20 rows (image rows [-2, 17])
constexpr int NT4 = RAW_W / 4;   // 34 float4 per raw row

// Per-batch snow mask (8 MB), __device__ global => no runtime allocation.
__device__ __align__(16) unsigned char g_mask[NB * IMG_H * IMG_W];

// ---------------------------------------------------------------------------
// Kernel 1: zero the mask (uint4 stores)
// ---------------------------------------------------------------------------
__global__ void zero_mask_kernel() {
    int i = blockIdx.x * blockDim.x + threadIdx.x;
    constexpr int N16 = NB * IMG_H * IMG_W / 16;
    uint4* p = reinterpret_cast<uint4*>(g_mask);
    if (i < N16) p[i] = make_uint4(0u, 0u, 0u, 0u);
}

// ---------------------------------------------------------------------------
// Kernel 2: scatter snow boxes. One thread per (batch, spot).
// ---------------------------------------------------------------------------
__global__ void scatter_kernel(const int* __restrict__ ys,
                               const int* __restrict__ xs,
                               const int* __restrict__ rs) {
    int i = blockIdx.x * blockDim.x + threadIdx.x;
    if (i >= NB * N_SPOTS) return;
    int b = i / N_SPOTS;
    int y = ys[i];
    int x = xs[i];
    int r = rs[i] + 1;
    unsigned char* m = g_mask + (size_t)b * IMG_H * IMG_W;
    int y0 = y - r; if (y0 < 0) y0 = 0;
    int y1 = y + r; if (y1 > IMG_H - 1) y1 = IMG_H - 1;
    int x0 = x - r; if (x0 < 0) x0 = 0;
    int x1 = x + r; if (x1 > IMG_W - 1) x1 = IMG_W - 1;
    for (int yy = y0; yy <= y1; yy++) {
        unsigned char* row = m + yy * IMG_W;
        for (int xx = x0; xx <= x1; xx++) row[xx] = 1;
    }
}

// ---------------------------------------------------------------------------
// Kernel 3: fused mask-substitute + separable 5x5 Gaussian + clip. Fully
// vectorized float4 path. Block 256 threads, tile 128(w) x 16(h).
//
// raw column c  <-> image column bx*128 + c - 4
// hf  column c  <-> image column bx*128 + c      (= raw column c + 4)
// raw/hf row r  <-> image row    by*16  + r - 2
// Horizontal tap for hf[c]: raw cols (c+2 .. c+6).
// ---------------------------------------------------------------------------
__global__ __launch_bounds__(256) void snow_blur_kernel(const float* __restrict__ x,
                                                        float* __restrict__ out) {
    __shared__ float raw[RAW_H * RAW_W];   // 20 x 136
    __shared__ float hf[RAW_H * TW];       // 20 x 128

    const int bx = blockIdx.x;
    const int by = blockIdx.y;
    const int bc = blockIdx.z;             // b*NC + c
    const int b = bc / NC;

    const float* __restrict__ xp = x + (size_t)bc * IMG_H * IMG_W;
    float* __restrict__ op = out + (size_t)bc * IMG_H * IMG_W;
    const unsigned char* __restrict__ mp = g_mask + (size_t)b * IMG_H * IMG_W;

    const int tid = threadIdx.x;
    const int gx0 = bx * TW - 4;           // float4-aligned raw base column
    const int gy0 = by * TH - 2;           // raw base row

    // ---- Phase 1: load masked input tile (float4 + uchar4), zero padding ----
    const bool interior_x = (bx != 0) && (bx != (IMG_W / TW) - 1);
    for (int t = tid; t < RAW_H * NT4; t += 256) {
        int r = t / NT4;
        int c4 = t - r * NT4;
        int gy = gy0 + r;
        int gx = gx0 + c4 * 4;
        float4 f = make_float4(0.f, 0.f, 0.f, 0.f);
        uchar4 m = make_uchar4(0, 0, 0, 0);
        if ((unsigned)gy < (unsigned)IMG_H) {
            const float* rowp = xp + gy * IMG_W;
            const unsigned char* mrow = mp + gy * IMG_W;
            if (interior_x || (gx >= 0 && gx + 3 < IMG_W)) {
                f = *reinterpret_cast<const float4*>(rowp + gx);
                m = *reinterpret_cast<const uchar4*>(mrow + gx);
            } else {
                float fv[4] = {0.f, 0.f, 0.f, 0.f};
                unsigned char mv[4] = {0, 0, 0, 0};
                #pragma unroll
                for (int k = 0; k < 4; k++) {
                    int g = gx + k;
                    if ((unsigned)g < (unsigned)IMG_W) { fv[k] = rowp[g]; mv[k] = mrow[g]; }
                }
                f = make_float4(fv[0], fv[1], fv[2], fv[3]);
                m = make_uchar4(mv[0], mv[1], mv[2], mv[3]);
            }
        }
        float4 v;
        v.x = m.x ? 0.95f : f.x;
        v.y = m.y ? 0.95f : f.y;
        v.z = m.z ? 0.95f : f.z;
        v.w = m.w ? 0.95f : f.w;
        *reinterpret_cast<float4*>(&raw[r * RAW_W + c4 * 4]) = v;
    }
    __syncthreads();

    // ---- Phase 2: horizontal filter, 4 outputs per task (3 aligned LDS.128) ----
    // hf[r][cs+j] centered at raw col cs+j+4, taps raw cols cs+j+2 .. cs+j+6.
    // Window for j=0..3: raw cols cs+2 .. cs+9  -> float4s at cs, cs+4, cs+8.
    for (int t = tid; t < RAW_H * (TW / 4); t += 256) {
        int r = t >> 5;                    // TW/4 == 32
        int cs = (t & 31) * 4;
        const float* rr = &raw[r * RAW_W + cs];
        float4 a = *reinterpret_cast<const float4*>(rr);        // cols cs+0..cs+3
        float4 bb = *reinterpret_cast<const float4*>(rr + 4);   // cols cs+4..cs+7
        float4 cc = *reinterpret_cast<const float4*>(rr + 8);   // cols cs+8..cs+11
        float4 o;
        o.x = G0 * a.z  + G1 * a.w  + G2 * bb.x + G1 * bb.y + G0 * bb.z;
        o.y = G0 * a.w  + G1 * bb.x + G2 * bb.y + G1 * bb.z + G0 * bb.w;
        o.z = G0 * bb.x + G1 * bb.y + G2 * bb.z + G1 * bb.w + G0 * cc.x;
        o.w = G0 * bb.y + G1 * bb.z + G2 * bb.w + G1 * cc.x + G0 * cc.y;
        *reinterpret_cast<float4*>(&hf[r * TW + cs]) = o;
    }
    __syncthreads();

    // ---- Phase 3: vertical filter, 4-wide x 2-row tasks, STG.128 out ----
    {
        const int cx = (tid & 31) * 4;
        const int r0 = (tid >> 5) * 2;     // 0,2,...,14
        const float* hc = &hf[r0 * TW + cx];
        float4 a0 = *reinterpret_cast<const float4*>(hc + 0 * TW);
        float4 a1 = *reinterpret_cast<const float4*>(hc + 1 * TW);
        float4 a2 = *reinterpret_cast<const float4*>(hc + 2 * TW);
        float4 a3 = *reinterpret_cast<const float4*>(hc + 3 * TW);
        float4 a4 = *reinterpret_cast<const float4*>(hc + 4 * TW);
        float4 a5 = *reinterpret_cast<const float4*>(hc + 5 * TW);

        float4 o0, o1;
        o0.x = G0 * a0.x + G1 * a1.x + G2 * a2.x + G1 * a3.x + G0 * a4.x;
        o0.y = G0 * a0.y + G1 * a1.y + G2 * a2.y + G1 * a3.y + G0 * a4.y;
        o0.z = G0 * a0.z + G1 * a1.z + G2 * a2.z + G1 * a3.z + G0 * a4.z;
        o0.w = G0 * a0.w + G1 * a1.w + G2 * a2.w + G1 * a3.w + G0 * a4.w;
        o1.x = G0 * a1.x + G1 * a2.x + G2 * a3.x + G1 * a4.x + G0 * a5.x;
        o1.y = G0 * a1.y + G1 * a2.y + G2 * a3.y + G1 * a4.y + G0 * a5.y;
        o1.z = G0 * a1.z + G1 * a2.z + G2 * a3.z + G1 * a4.z + G0 * a5.z;
        o1.w = G0 * a1.w + G1 * a2.w + G2 * a3.w + G1 * a4.w + G0 * a5.w;

        o0.x = fminf(fmaxf(o0.x, 0.f), 1.f);
        o0.y = fminf(fmaxf(o0.y, 0.f), 1.f);
        o0.z = fminf(fmaxf(o0.z, 0.f), 1.f);
        o0.w = fminf(fmaxf(o0.w, 0.f), 1.f);
        o1.x = fminf(fmaxf(o1.x, 0.f), 1.f);
        o1.y = fminf(fmaxf(o1.y, 0.f), 1.f);
        o1.z = fminf(fmaxf(o1.z, 0.f), 1.f);
        o1.w = fminf(fmaxf(o1.w, 0.f), 1.f);

        const int gy = by * TH + r0;
        const int gx = bx * TW + cx;
        float* po = op + gy * IMG_W + gx;
        *reinterpret_cast<float4*>(po) = o0;
        *reinterpret_cast<float4*>(po + IMG_W) = o1;
    }
}

// ---------------------------------------------------------------------------
// Launch
// ---------------------------------------------------------------------------
extern "C" void kernel_launch(void* const* d_in, const int* in_sizes, int n_in,
                              void* d_out, int out_size) {
    const float* x  = (const float*)d_in[0];
    const int*   ys = (const int*)d_in[1];
    const int*   xs = (const int*)d_in[2];
    const int*   rs = (const int*)d_in[3];
    float* out = (float*)d_out;

    constexpr int N16 = NB * IMG_H * IMG_W / 16;
    zero_mask_kernel<<<(N16 + 255) / 256, 256>>>();

    constexpr int NSP = NB * N_SPOTS;
    scatter_kernel<<<(NSP + 255) / 256, 256>>>(ys, xs, rs);

    dim3 grid(IMG_W / TW, IMG_H / TH, NB * NC);
    snow_blur_kernel<<<grid, 256>>>(x, out);
}

// round 4
// speedup vs baseline: 1.8480x; 1.1598x over previous
#include <cuda_runtime.h>
#include <stdint.h>

// Problem constants
constexpr int NB = 8;
constexpr int NC = 3;
constexpr int IMG_H = 1024;
constexpr int IMG_W = 1024;
constexpr int N_SPOTS = 15728;

// Gaussian 1D weights for ksize=5, sigma=1.5 (normalized)
#define G0 0.12007838424f
#define G1 0.23388075658f
#define G2 0.29208171834f

// Tile geometry for the conv kernel
constexpr int TW = 128;          // output tile width
constexpr int TH = 32;           // output tile height
constexpr int RAW_W = TW + 8;    // 136 floats per raw row (image cols [-4, 131])
constexpr int RAW_H = TH + 4;    // 36 rows (image rows [-2, 33])
constexpr int NT4 = RAW_W / 4;   // 34 float4 per raw row
constexpr int NTHR = 512;

// Per-batch snow mask (8 MB), __device__ global => no runtime allocation.
__device__ __align__(16) unsigned char g_mask[NB * IMG_H * IMG_W];

// ---------------------------------------------------------------------------
// Kernel 1: zero the mask. 1024 blocks x 256 threads, 32 B per thread.
// ---------------------------------------------------------------------------
__global__ void zero_mask_kernel() {
    int i = blockIdx.x * blockDim.x + threadIdx.x;   // 0 .. 262143
    uint4* p = reinterpret_cast<uint4*>(g_mask) + i * 2;
    p[0] = make_uint4(0u, 0u, 0u, 0u);
    p[1] = make_uint4(0u, 0u, 0u, 0u);
}

// ---------------------------------------------------------------------------
// Kernel 2: scatter snow boxes, ONE WARP PER SPOT. Lanes cover one box row
// per store instruction -> contiguous bytes -> 1 L1tex wavefront per row
// instead of 1 per pixel.
// ---------------------------------------------------------------------------
__global__ void scatter_kernel(const int* __restrict__ ys,
                               const int* __restrict__ xs,
                               const int* __restrict__ rs) {
    int w = (blockIdx.x * blockDim.x + threadIdx.x) >> 5;   // global warp id
    int lane = threadIdx.x & 31;
    if (w >= NB * N_SPOTS) return;
    int b = w / N_SPOTS;
    int y = ys[w];            // broadcast load (all lanes same address)
    int x = xs[w];
    int r = rs[w] + 1;
    int y0 = y - r; if (y0 < 0) y0 = 0;
    int y1 = y + r; if (y1 > IMG_H - 1) y1 = IMG_H - 1;
    int x0 = x - r; if (x0 < 0) x0 = 0;
    int x1 = x + r; if (x1 > IMG_W - 1) x1 = IMG_W - 1;
    unsigned char* m = g_mask + (size_t)b * IMG_H * IMG_W;
    int px = x0 + lane;
    bool act = (px <= x1);
    for (int yy = y0; yy <= y1; yy++) {
        if (act) m[yy * IMG_W + px] = 1;
    }
}

// ---------------------------------------------------------------------------
// Kernel 3: fused mask-substitute + separable 5x5 Gaussian + clip.
// Block 512 threads, tile 128(w) x 32(h). float4 everywhere.
//
// raw column c  <-> image column bx*128 + c - 4
// hf  column c  <-> image column bx*128 + c      (= raw column c + 4)
// raw/hf row r  <-> image row    by*32  + r - 2
// Horizontal tap for hf[c]: raw cols (c+2 .. c+6).
// ---------------------------------------------------------------------------
__global__ __launch_bounds__(NTHR) void snow_blur_kernel(const float* __restrict__ x,
                                                         float* __restrict__ out) {
    __shared__ float raw[RAW_H * RAW_W];   // 36 x 136
    __shared__ float hf[RAW_H * TW];       // 36 x 128

    const int bx = blockIdx.x;
    const int by = blockIdx.y;
    const int bc = blockIdx.z;             // b*NC + c
    const int b = bc / NC;

    const float* __restrict__ xp = x + (size_t)bc * IMG_H * IMG_W;
    float* __restrict__ op = out + (size_t)bc * IMG_H * IMG_W;
    const unsigned char* __restrict__ mp = g_mask + (size_t)b * IMG_H * IMG_W;

    const int tid = threadIdx.x;
    const int gx0 = bx * TW - 4;           // float4-aligned raw base column
    const int gy0 = by * TH - 2;           // raw base row

    // ---- Phase 1: load masked input tile (float4 + uchar4), zero padding ----
    constexpr int P1_TASKS = RAW_H * NT4;  // 1224
    const bool interior = (bx >= 1) && (bx <= (IMG_W / TW) - 2) &&
                          (by >= 1) && (by <= (IMG_H / TH) - 2);
    if (interior) {
        // No bounds checks anywhere; ptxas can batch loads for high MLP.
        #pragma unroll
        for (int it = 0; it < 3; it++) {
            int t = tid + it * NTHR;
            if (it == 2 && t >= P1_TASKS) break;
            int r = t / NT4;
            int c4 = t - r * NT4;
            int idx = (gy0 + r) * IMG_W + gx0 + c4 * 4;
            float4 f = *reinterpret_cast<const float4*>(xp + idx);
            uchar4 m = *reinterpret_cast<const uchar4*>(mp + idx);
            float4 v;
            v.x = m.x ? 0.95f : f.x;
            v.y = m.y ? 0.95f : f.y;
            v.z = m.z ? 0.95f : f.z;
            v.w = m.w ? 0.95f : f.w;
            *reinterpret_cast<float4*>(&raw[r * RAW_W + c4 * 4]) = v;
        }
    } else {
        for (int t = tid; t < P1_TASKS; t += NTHR) {
            int r = t / NT4;
            int c4 = t - r * NT4;
            int gy = gy0 + r;
            int gx = gx0 + c4 * 4;
            float4 f = make_float4(0.f, 0.f, 0.f, 0.f);
            uchar4 m = make_uchar4(0, 0, 0, 0);
            if ((unsigned)gy < (unsigned)IMG_H) {
                const float* rowp = xp + gy * IMG_W;
                const unsigned char* mrow = mp + gy * IMG_W;
                if (gx >= 0 && gx + 3 < IMG_W) {
                    f = *reinterpret_cast<const float4*>(rowp + gx);
                    m = *reinterpret_cast<const uchar4*>(mrow + gx);
                } else {
                    float fv[4] = {0.f, 0.f, 0.f, 0.f};
                    unsigned char mv[4] = {0, 0, 0, 0};
                    #pragma unroll
                    for (int k = 0; k < 4; k++) {
                        int g = gx + k;
                        if ((unsigned)g < (unsigned)IMG_W) { fv[k] = rowp[g]; mv[k] = mrow[g]; }
                    }
                    f = make_float4(fv[0], fv[1], fv[2], fv[3]);
                    m = make_uchar4(mv[0], mv[1], mv[2], mv[3]);
                }
            }
            float4 v;
            v.x = m.x ? 0.95f : f.x;
            v.y = m.y ? 0.95f : f.y;
            v.z = m.z ? 0.95f : f.z;
            v.w = m.w ? 0.95f : f.w;
            *reinterpret_cast<float4*>(&raw[r * RAW_W + c4 * 4]) = v;
        }
    }
    __syncthreads();

    // ---- Phase 2: horizontal filter, 4 outputs per task (3 aligned LDS.128) ----
    // hf[r][cs+j] centered at raw col cs+j+4, taps raw cols cs+j+2 .. cs+j+6.
    constexpr int P2_TASKS = RAW_H * (TW / 4);   // 1152
    #pragma unroll
    for (int it = 0; it < 3; it++) {
        int t = tid + it * NTHR;
        if (it == 2 && t >= P2_TASKS) break;
        int r = t >> 5;                    // TW/4 == 32
        int cs = (t & 31) * 4;
        const float* rr = &raw[r * RAW_W + cs];
        float4 a = *reinterpret_cast<const float4*>(rr);        // cols cs+0..cs+3
        float4 bb = *reinterpret_cast<const float4*>(rr + 4);   // cols cs+4..cs+7
        float4 cc = *reinterpret_cast<const float4*>(rr + 8);   // cols cs+8..cs+11
        float4 o;
        o.x = G0 * a.z  + G1 * a.w  + G2 * bb.x + G1 * bb.y + G0 * bb.z;
        o.y = G0 * a.w  + G1 * bb.x + G2 * bb.y + G1 * bb.z + G0 * bb.w;
        o.z = G0 * bb.x + G1 * bb.y + G2 * bb.z + G1 * bb.w + G0 * cc.x;
        o.w = G0 * bb.y + G1 * bb.z + G2 * bb.w + G1 * cc.x + G0 * cc.y;
        *reinterpret_cast<float4*>(&hf[r * TW + cs]) = o;
    }
    __syncthreads();

    // ---- Phase 3: vertical filter, one 4-wide x 2-row task per thread ----
    {
        const int cx = (tid & 31) * 4;
        const int r0 = (tid >> 5) * 2;     // 0,2,...,30
        const float* hc = &hf[r0 * TW + cx];
        float4 a0 = *reinterpret_cast<const float4*>(hc + 0 * TW);
        float4 a1 = *reinterpret_cast<const float4*>(hc + 1 * TW);
        float4 a2 = *reinterpret_cast<const float4*>(hc + 2 * TW);
        float4 a3 = *reinterpret_cast<const float4*>(hc + 3 * TW);
        float4 a4 = *reinterpret_cast<const float4*>(hc + 4 * TW);
        float4 a5 = *reinterpret_cast<const float4*>(hc + 5 * TW);

        float4 o0, o1;
        o0.x = G0 * a0.x + G1 * a1.x + G2 * a2.x + G1 * a3.x + G0 * a4.x;
        o0.y = G0 * a0.y + G1 * a1.y + G2 * a2.y + G1 * a3.y + G0 * a4.y;
        o0.z = G0 * a0.z + G1 * a1.z + G2 * a2.z + G1 * a3.z + G0 * a4.z;
        o0.w = G0 * a0.w + G1 * a1.w + G2 * a2.w + G1 * a3.w + G0 * a4.w;
        o1.x = G0 * a1.x + G1 * a2.x + G2 * a3.x + G1 * a4.x + G0 * a5.x;
        o1.y = G0 * a1.y + G1 * a2.y + G2 * a3.y + G1 * a4.y + G0 * a5.y;
        o1.z = G0 * a1.z + G1 * a2.z + G2 * a3.z + G1 * a4.z + G0 * a5.z;
        o1.w = G0 * a1.w + G1 * a2.w + G2 * a3.w + G1 * a4.w + G0 * a5.w;

        o0.x = fminf(fmaxf(o0.x, 0.f), 1.f);
        o0.y = fminf(fmaxf(o0.y, 0.f), 1.f);
        o0.z = fminf(fmaxf(o0.z, 0.f), 1.f);
        o0.w = fminf(fmaxf(o0.w, 0.f), 1.f);
        o1.x = fminf(fmaxf(o1.x, 0.f), 1.f);
        o1.y = fminf(fmaxf(o1.y, 0.f), 1.f);
        o1.z = fminf(fmaxf(o1.z, 0.f), 1.f);
        o1.w = fminf(fmaxf(o1.w, 0.f), 1.f);

        const int gy = by * TH + r0;
        const int gx = bx * TW + cx;
        float* po = op + gy * IMG_W + gx;
        *reinterpret_cast<float4*>(po) = o0;
        *reinterpret_cast<float4*>(po + IMG_W) = o1;
    }
}

// ---------------------------------------------------------------------------
// Launch
// ---------------------------------------------------------------------------
extern "C" void kernel_launch(void* const* d_in, const int* in_sizes, int n_in,
                              void* d_out, int out_size) {
    const float* x  = (const float*)d_in[0];
    const int*   ys = (const int*)d_in[1];
    const int*   xs = (const int*)d_in[2];
    const int*   rs = (const int*)d_in[3];
    float* out = (float*)d_out;

    // 1) zero mask: 8MB / 32B per thread = 262144 threads
    zero_mask_kernel<<<1024, 256>>>();

    // 2) scatter: one warp per spot, 8 warps per block
    constexpr int NSP = NB * N_SPOTS;                  // 125824 warps
    scatter_kernel<<<(NSP * 32 + 255) / 256, 256>>>(ys, xs, rs);

    // 3) fused mask + separable blur + clip
    dim3 grid(IMG_W / TW, IMG_H / TH, NB * NC);
    snow_blur_kernel<<<grid, NTHR>>>(x, out);
}

// round 5
// speedup vs baseline: 2.5067x; 1.3564x over previous
#include <cuda_runtime.h>
#include <stdint.h>

// Problem constants
constexpr int NB = 8;
constexpr int NC = 3;
constexpr int IMG_H = 1024;
constexpr int IMG_W = 1024;
constexpr int N_SPOTS = 15728;

// Gaussian 1D weights for ksize=5, sigma=1.5 (normalized)
#define G0 0.12007838424f
#define G1 0.23388075658f
#define G2 0.29208171834f

// Conv tile geometry
constexpr int TW = 128;           // tile width  (one warp row = 32 lanes x 4 cols)
constexpr int TH = 64;            // tile height
constexpr int HF_H = TH + 4;      // 68 hf rows (vertical halo 2+2)
constexpr int NTHR = 512;         // 16 warps

// Bit mask: 1 bit per pixel. 8 * 1024 * 32 words = 1 MB.
constexpr int WPR = IMG_W / 32;   // 32 words per image row
__device__ __align__(16) unsigned int g_maskbits[NB * IMG_H * WPR];

// ---------------------------------------------------------------------------
// Kernel 1: zero the bit mask (1 MB). 256 blocks x 256 threads x 1 uint4.
// ---------------------------------------------------------------------------
__global__ void zero_mask_kernel() {
    int i = blockIdx.x * blockDim.x + threadIdx.x;   // 0 .. 65535
    reinterpret_cast<uint4*>(g_maskbits)[i] = make_uint4(0u, 0u, 0u, 0u);
}

// ---------------------------------------------------------------------------
// Kernel 2: scatter snow boxes into the bit mask. One thread per spot.
// Each box row (width <= 7 bits) is 1 or 2 atomicOr (straddle) -> REDG.OR.
// ---------------------------------------------------------------------------
__global__ void scatter_kernel(const int* __restrict__ ys,
                               const int* __restrict__ xs,
                               const int* __restrict__ rs) {
    int i = blockIdx.x * blockDim.x + threadIdx.x;
    if (i >= NB * N_SPOTS) return;
    int b = i / N_SPOTS;
    int y = ys[i];
    int x = xs[i];
    int r = rs[i] + 1;                       // 1..3
    int y0 = max(y - r, 0);
    int y1 = min(y + r, IMG_H - 1);
    int x0 = max(x - r, 0);
    int x1 = min(x + r, IMG_W - 1);
    int width = x1 - x0 + 1;                 // 1..7
    int s0 = x0 & 31;
    unsigned long long m64 = ((1ULL << width) - 1ULL) << s0;
    unsigned int m0 = (unsigned int)m64;
    unsigned int m1 = (unsigned int)(m64 >> 32);
    unsigned int* base = g_maskbits + b * IMG_H * WPR + (x0 >> 5);
    for (int yy = y0; yy <= y1; yy++) {
        unsigned int* p = base + yy * WPR;
        atomicOr(p, m0);
        if (m1) atomicOr(p + 1, m1);         // straddle never exceeds row end
    }
}

// ---------------------------------------------------------------------------
// Kernel 3: fused mask-substitute + separable 5x5 Gaussian + clip.
// Block: 512 threads (16 warps). Tile: 128(w) x 64(h).
//
// Phase A (warp-per-row): global float4 load + bitmask substitute + horizontal
//   filter via 4 warp shuffles (lane l owns image cols colbase+4l..+3; window
//   borrowed from lanes l-1 / l+1; lanes 0/31 patch halo with predicated
//   loads). Result -> hf smem (only smem array, 35 KB).
// Phase B: vertical filter, 4 output rows x 4 cols per thread, STG.128.
//
// hf row r <-> image row by*64 + r - 2.  out row j needs hf rows j..j+4.
// ---------------------------------------------------------------------------
struct RowVals { float4 f; float p2, p3, n0, n1; };

__device__ __forceinline__ void hrow(const float* __restrict__ xp,
                                     const unsigned int* __restrict__ mb,
                                     float* __restrict__ hf,
                                     int r, int by, int colbase, int lane) {
    int gy = by * TH + r - 2;
    float4 f = make_float4(0.f, 0.f, 0.f, 0.f);
    float p2 = 0.f, p3 = 0.f, n0 = 0.f, n1 = 0.f;
    if ((unsigned)gy < (unsigned)IMG_H) {
        const float* rowp = xp + gy * IMG_W;
        const unsigned int* mrow = mb + gy * WPR;
        int cl = colbase + lane * 4;
        f = *reinterpret_cast<const float4*>(rowp + cl);
        unsigned int w = mrow[cl >> 5];
        int s = (lane & 7) * 4;
        if ((w >> s) & 1u)       f.x = 0.95f;
        if ((w >> (s + 1)) & 1u) f.y = 0.95f;
        if ((w >> (s + 2)) & 1u) f.z = 0.95f;
        if ((w >> (s + 3)) & 1u) f.w = 0.95f;
        if (lane == 0 && colbase > 0) {
            float4 h = *reinterpret_cast<const float4*>(rowp + colbase - 4);
            unsigned int wl = mrow[(colbase - 4) >> 5];
            p2 = ((wl >> 30) & 1u) ? 0.95f : h.z;
            p3 = ((wl >> 31) & 1u) ? 0.95f : h.w;
        }
        if (lane == 31 && colbase + TW < IMG_W) {
            float4 h = *reinterpret_cast<const float4*>(rowp + colbase + TW);
            unsigned int wr = mrow[(colbase + TW) >> 5];
            n0 = (wr & 1u) ? 0.95f : h.x;
            n1 = ((wr >> 1) & 1u) ? 0.95f : h.y;
        }
    }
    // Borrow window edges from neighbor lanes
    float sz = __shfl_up_sync(0xffffffffu, f.z, 1);
    float sw = __shfl_up_sync(0xffffffffu, f.w, 1);
    float sx = __shfl_down_sync(0xffffffffu, f.x, 1);
    float sy = __shfl_down_sync(0xffffffffu, f.y, 1);
    if (lane != 0)  { p2 = sz; p3 = sw; }
    if (lane != 31) { n0 = sx; n1 = sy; }

    float4 o;
    o.x = G0 * p2  + G1 * p3  + G2 * f.x + G1 * f.y + G0 * f.z;
    o.y = G0 * p3  + G1 * f.x + G2 * f.y + G1 * f.z + G0 * f.w;
    o.z = G0 * f.x + G1 * f.y + G2 * f.z + G1 * f.w + G0 * n0;
    o.w = G0 * f.y + G1 * f.z + G2 * f.w + G1 * n0  + G0 * n1;
    *reinterpret_cast<float4*>(&hf[r * TW + lane * 4]) = o;
}

__global__ __launch_bounds__(NTHR) void snow_blur_kernel(const float* __restrict__ x,
                                                         float* __restrict__ out) {
    __shared__ float hf[HF_H * TW];      // 68 x 128 x 4B = 34816 B

    const int bx = blockIdx.x;
    const int by = blockIdx.y;
    const int bc = blockIdx.z;           // b*NC + c
    const int b = bc / NC;

    const float* __restrict__ xp = x + (size_t)bc * IMG_H * IMG_W;
    float* __restrict__ op = out + (size_t)bc * IMG_H * IMG_W;
    const unsigned int* __restrict__ mb = g_maskbits + b * IMG_H * WPR;

    const int tid = threadIdx.x;
    const int wid = tid >> 5;
    const int lane = tid & 31;
    const int colbase = bx * TW;

    // ---- Phase A: horizontal rows (4 unconditional + guarded tail) ----
    hrow(xp, mb, hf, wid,      by, colbase, lane);
    hrow(xp, mb, hf, wid + 16, by, colbase, lane);
    hrow(xp, mb, hf, wid + 32, by, colbase, lane);
    hrow(xp, mb, hf, wid + 48, by, colbase, lane);
    if (wid < HF_H - 64)                 // warps 0..3 do rows 64..67
        hrow(xp, mb, hf, wid + 64, by, colbase, lane);
    __syncthreads();

    // ---- Phase B: vertical filter, 4 output rows x 4 cols per thread ----
    {
        const int r0 = wid * 4;          // 0,4,...,60
        const float* hc = &hf[r0 * TW + lane * 4];
        float4 a0 = *reinterpret_cast<const float4*>(hc + 0 * TW);
        float4 a1 = *reinterpret_cast<const float4*>(hc + 1 * TW);
        float4 a2 = *reinterpret_cast<const float4*>(hc + 2 * TW);
        float4 a3 = *reinterpret_cast<const float4*>(hc + 3 * TW);
        float4 a4 = *reinterpret_cast<const float4*>(hc + 4 * TW);
        float4 a5 = *reinterpret_cast<const float4*>(hc + 5 * TW);
        float4 a6 = *reinterpret_cast<const float4*>(hc + 6 * TW);
        float4 a7 = *reinterpret_cast<const float4*>(hc + 7 * TW);

        const int gy = by * TH + r0;
        float* po = op + gy * IMG_W + colbase + lane * 4;

        #define VOUT(i, A, B, C, D, E)                                          \
        {                                                                       \
            float4 o;                                                           \
            o.x = G0 * A.x + G1 * B.x + G2 * C.x + G1 * D.x + G0 * E.x;         \
            o.y = G0 * A.y + G1 * B.y + G2 * C.y + G1 * D.y + G0 * E.y;         \
            o.z = G0 * A.z + G1 * B.z + G2 * C.z + G1 * D.z + G0 * E.z;         \
            o.w = G0 * A.w + G1 * B.w + G2 * C.w + G1 * D.w + G0 * E.w;         \
            o.x = fminf(fmaxf(o.x, 0.f), 1.f);                                  \
            o.y = fminf(fmaxf(o.y, 0.f), 1.f);                                  \
            o.z = fminf(fmaxf(o.z, 0.f), 1.f);                                  \
            o.w = fminf(fmaxf(o.w, 0.f), 1.f);                                  \
            *reinterpret_cast<float4*>(po + (i) * IMG_W) = o;                   \
        }
        VOUT(0, a0, a1, a2, a3, a4)
        VOUT(1, a1, a2, a3, a4, a5)
        VOUT(2, a2, a3, a4, a5, a6)
        VOUT(3, a3, a4, a5, a6, a7)
        #undef VOUT
    }
}

// ---------------------------------------------------------------------------
// Launch
// ---------------------------------------------------------------------------
extern "C" void kernel_launch(void* const* d_in, const int* in_sizes, int n_in,
                              void* d_out, int out_size) {
    const float* x  = (const float*)d_in[0];
    const int*   ys = (const int*)d_in[1];
    const int*   xs = (const int*)d_in[2];
    const int*   rs = (const int*)d_in[3];
    float* out = (float*)d_out;

    // 1) zero 1 MB bit mask: 65536 uint4
    zero_mask_kernel<<<256, 256>>>();

    // 2) scatter: one thread per spot, atomicOr rows
    constexpr int NSP = NB * N_SPOTS;
    scatter_kernel<<<(NSP + 255) / 256, 256>>>(ys, xs, rs);

    // 3) fused mask + separable blur + clip
    dim3 grid(IMG_W / TW, IMG_H / TH, NB * NC);
    snow_blur_kernel<<<grid, NTHR>>>(x, out);
}

// round 6
// speedup vs baseline: 2.6949x; 1.0751x over previous
#include <cuda_runtime.h>
#include <stdint.h>

// Problem constants
constexpr int NB = 8;
constexpr int NC = 3;
constexpr int IMG_H = 1024;
constexpr int IMG_W = 1024;
constexpr int N_SPOTS = 15728;

// Gaussian 1D weights for ksize=5, sigma=1.5 (normalized)
#define G0 0.12007838424f
#define G1 0.23388075658f
#define G2 0.29208171834f

// Conv tile geometry
constexpr int TW = 128;           // tile width  (one warp row = 32 lanes x 4 cols)
constexpr int TH = 32;            // tile height
constexpr int HF_H = TH + 4;      // 36 hf rows (vertical halo 2+2)
constexpr int NTHR = 256;         // 8 warps

// Bit mask: 1 bit per pixel. 8 * 1024 * 32 words = 1 MB.
constexpr int WPR = IMG_W / 32;   // 32 words per image row
__device__ __align__(16) unsigned int g_maskbits[NB * IMG_H * WPR];

// ---------------------------------------------------------------------------
// Kernel 1: zero the bit mask (1 MB).
// ---------------------------------------------------------------------------
__global__ void zero_mask_kernel() {
    int i = blockIdx.x * blockDim.x + threadIdx.x;   // 0 .. 65535
    reinterpret_cast<uint4*>(g_maskbits)[i] = make_uint4(0u, 0u, 0u, 0u);
}

// ---------------------------------------------------------------------------
// Kernel 2: scatter snow boxes into the bit mask. One thread per spot.
// Each box row (width <= 7 bits) is 1 or 2 atomicOr (straddle) -> REDG.OR.
// ---------------------------------------------------------------------------
__global__ void scatter_kernel(const int* __restrict__ ys,
                               const int* __restrict__ xs,
                               const int* __restrict__ rs) {
    int i = blockIdx.x * blockDim.x + threadIdx.x;
    if (i >= NB * N_SPOTS) return;
    int b = i / N_SPOTS;
    int y = ys[i];
    int x = xs[i];
    int r = rs[i] + 1;                       // 1..3
    int y0 = max(y - r, 0);
    int y1 = min(y + r, IMG_H - 1);
    int x0 = max(x - r, 0);
    int x1 = min(x + r, IMG_W - 1);
    int width = x1 - x0 + 1;                 // 1..7
    int s0 = x0 & 31;
    unsigned long long m64 = ((1ULL << width) - 1ULL) << s0;
    unsigned int m0 = (unsigned int)m64;
    unsigned int m1 = (unsigned int)(m64 >> 32);
    unsigned int* base = g_maskbits + b * IMG_H * WPR + (x0 >> 5);
    int nrows = y1 - y0 + 1;                 // 1..7
    #pragma unroll
    for (int k = 0; k < 7; k++) {
        if (k < nrows) {
            unsigned int* p = base + (y0 + k) * WPR;
            atomicOr(p, m0);
            if (m1) atomicOr(p + 1, m1);     // straddle never exceeds row end
        }
    }
}

// ---------------------------------------------------------------------------
// Kernel 3: fused mask-substitute + separable 5x5 Gaussian + clip.
// Block: 256 threads (8 warps). Tile: 128(w) x 32(h). 8 blocks/SM.
//
// Phase A (warp-per-row): global float4 load + bitmask substitute + horizontal
//   filter via 4 warp shuffles. Result -> hf smem (18.4 KB, only smem array).
// Phase B: vertical filter, 4 output rows x 4 cols per thread, STG.128.
//
// hf row r <-> image row by*32 + r - 2.  out row j needs hf rows j..j+4.
// ---------------------------------------------------------------------------
__device__ __forceinline__ void hrow(const float* __restrict__ xp,
                                     const unsigned int* __restrict__ mb,
                                     float* __restrict__ hf,
                                     int r, int by, int colbase, int lane) {
    int gy = by * TH + r - 2;
    float4 f = make_float4(0.f, 0.f, 0.f, 0.f);
    float p2 = 0.f, p3 = 0.f, n0 = 0.f, n1 = 0.f;
    if ((unsigned)gy < (unsigned)IMG_H) {
        const float* rowp = xp + gy * IMG_W;
        const unsigned int* mrow = mb + gy * WPR;
        int cl = colbase + lane * 4;
        f = *reinterpret_cast<const float4*>(rowp + cl);
        unsigned int w = mrow[cl >> 5];
        int s = (lane & 7) * 4;
        if ((w >> s) & 1u)       f.x = 0.95f;
        if ((w >> (s + 1)) & 1u) f.y = 0.95f;
        if ((w >> (s + 2)) & 1u) f.z = 0.95f;
        if ((w >> (s + 3)) & 1u) f.w = 0.95f;
        if (lane == 0 && colbase > 0) {
            float4 h = *reinterpret_cast<const float4*>(rowp + colbase - 4);
            unsigned int wl = mrow[(colbase - 4) >> 5];
            p2 = ((wl >> 30) & 1u) ? 0.95f : h.z;
            p3 = ((wl >> 31) & 1u) ? 0.95f : h.w;
        }
        if (lane == 31 && colbase + TW < IMG_W) {
            float4 h = *reinterpret_cast<const float4*>(rowp + colbase + TW);
            unsigned int wr = mrow[(colbase + TW) >> 5];
            n0 = (wr & 1u) ? 0.95f : h.x;
            n1 = ((wr >> 1) & 1u) ? 0.95f : h.y;
        }
    }
    // Borrow window edges from neighbor lanes
    float sz = __shfl_up_sync(0xffffffffu, f.z, 1);
    float sw = __shfl_up_sync(0xffffffffu, f.w, 1);
    float sx = __shfl_down_sync(0xffffffffu, f.x, 1);
    float sy = __shfl_down_sync(0xffffffffu, f.y, 1);
    if (lane != 0)  { p2 = sz; p3 = sw; }
    if (lane != 31) { n0 = sx; n1 = sy; }

    float4 o;
    o.x = G0 * p2  + G1 * p3  + G2 * f.x + G1 * f.y + G0 * f.z;
    o.y = G0 * p3  + G1 * f.x + G2 * f.y + G1 * f.z + G0 * f.w;
    o.z = G0 * f.x + G1 * f.y + G2 * f.z + G1 * f.w + G0 * n0;
    o.w = G0 * f.y + G1 * f.z + G2 * f.w + G1 * n0  + G0 * n1;
    *reinterpret_cast<float4*>(&hf[r * TW + lane * 4]) = o;
}

__global__ __launch_bounds__(NTHR) void snow_blur_kernel(const float* __restrict__ x,
                                                         float* __restrict__ out) {
    __shared__ float hf[HF_H * TW];      // 36 x 128 x 4B = 18432 B

    const int bx = blockIdx.x;
    const int by = blockIdx.y;
    const int bc = blockIdx.z;           // b*NC + c
    const int b = bc / NC;

    const float* __restrict__ xp = x + (size_t)bc * IMG_H * IMG_W;
    float* __restrict__ op = out + (size_t)bc * IMG_H * IMG_W;
    const unsigned int* __restrict__ mb = g_maskbits + b * IMG_H * WPR;

    const int tid = threadIdx.x;
    const int wid = tid >> 5;
    const int lane = tid & 31;
    const int colbase = bx * TW;

    // ---- Phase A: horizontal rows (4 unconditional + guarded tail) ----
    hrow(xp, mb, hf, wid,      by, colbase, lane);
    hrow(xp, mb, hf, wid + 8,  by, colbase, lane);
    hrow(xp, mb, hf, wid + 16, by, colbase, lane);
    hrow(xp, mb, hf, wid + 24, by, colbase, lane);
    if (wid < HF_H - 32)                 // warps 0..3 do rows 32..35
        hrow(xp, mb, hf, wid + 32, by, colbase, lane);
    __syncthreads();

    // ---- Phase B: vertical filter, 4 output rows x 4 cols per thread ----
    {
        const int r0 = wid * 4;          // 0,4,...,28
        const float* hc = &hf[r0 * TW + lane * 4];
        float4 a0 = *reinterpret_cast<const float4*>(hc + 0 * TW);
        float4 a1 = *reinterpret_cast<const float4*>(hc + 1 * TW);
        float4 a2 = *reinterpret_cast<const float4*>(hc + 2 * TW);
        float4 a3 = *reinterpret_cast<const float4*>(hc + 3 * TW);
        float4 a4 = *reinterpret_cast<const float4*>(hc + 4 * TW);
        float4 a5 = *reinterpret_cast<const float4*>(hc + 5 * TW);
        float4 a6 = *reinterpret_cast<const float4*>(hc + 6 * TW);
        float4 a7 = *reinterpret_cast<const float4*>(hc + 7 * TW);

        const int gy = by * TH + r0;
        float* po = op + gy * IMG_W + colbase + lane * 4;

        #define VOUT(i, A, B, C, D, E)                                          \
        {                                                                       \
            float4 o;                                                           \
            o.x = G0 * A.x + G1 * B.x + G2 * C.x + G1 * D.x + G0 * E.x;         \
            o.y = G0 * A.y + G1 * B.y + G2 * C.y + G1 * D.y + G0 * E.y;         \
            o.z = G0 * A.z + G1 * B.z + G2 * C.z + G1 * D.z + G0 * E.z;         \
            o.w = G0 * A.w + G1 * B.w + G2 * C.w + G1 * D.w + G0 * E.w;         \
            o.x = fminf(fmaxf(o.x, 0.f), 1.f);                                  \
            o.y = fminf(fmaxf(o.y, 0.f), 1.f);                                  \
            o.z = fminf(fmaxf(o.z, 0.f), 1.f);                                  \
            o.w = fminf(fmaxf(o.w, 0.f), 1.f);                                  \
            *reinterpret_cast<float4*>(po + (i) * IMG_W) = o;                   \
        }
        VOUT(0, a0, a1, a2, a3, a4)
        VOUT(1, a1, a2, a3, a4, a5)
        VOUT(2, a2, a3, a4, a5, a6)
        VOUT(3, a3, a4, a5, a6, a7)
        #undef VOUT
    }
}

// ---------------------------------------------------------------------------
// Launch
// ---------------------------------------------------------------------------
extern "C" void kernel_launch(void* const* d_in, const int* in_sizes, int n_in,
                              void* d_out, int out_size) {
    const float* x  = (const float*)d_in[0];
    const int*   ys = (const int*)d_in[1];
    const int*   xs = (const int*)d_in[2];
    const int*   rs = (const int*)d_in[3];
    float* out = (float*)d_out;

    // 1) zero 1 MB bit mask: 65536 uint4
    zero_mask_kernel<<<256, 256>>>();

    // 2) scatter: one thread per spot, atomicOr rows
    constexpr int NSP = NB * N_SPOTS;
    scatter_kernel<<<(NSP + 255) / 256, 256>>>(ys, xs, rs);

    // 3) fused mask + separable blur + clip
    dim3 grid(IMG_W / TW, IMG_H / TH, NB * NC);
    snow_blur_kernel<<<grid, NTHR>>>(x, out);
}